// round 5
// baseline (speedup 1.0000x reference)
#include <cuda_runtime.h>
#include <cstdint>

#define BB 64
#define TT 4096
#define HH 15
#define EE 15
#define GG 60   /* 4*H */
#define TCH 32
#define UU 8    /* prefetch depth (steps) in the recurrence */

// Gate preacts: one float4 per (t, dir, batch-pair, lane):
//   lane = grp*16 + j;  float4 = {gA(b0), gB(b0), gA(b1), gB(b1)}
//   grp0: gA=i_j, gB=f_j ; grp1: gA=g_j, gB=o_j
// j==15 slots never written -> stay zero. Padded 2*UU timesteps for prefetch.
__device__ float4 g_xg[(size_t)(TT + 2 * UU) * 2 * 32 * 32];
// Hidden states, [b][j][t] layout. Backward stored in step-time (rev at read).
__device__ float g_hsf[(size_t)BB * 16 * TT];
__device__ float g_hsbr[(size_t)BB * 16 * TT];

typedef unsigned long long ull;

__device__ __forceinline__ ull pack2(float lo, float hi) {
    ull r; asm("mov.b64 %0, {%1,%2};" : "=l"(r) : "f"(lo), "f"(hi)); return r;
}
__device__ __forceinline__ void unpack2(float& lo, float& hi, ull v) {
    asm("mov.b64 {%0,%1}, %2;" : "=f"(lo), "=f"(hi) : "l"(v));
}
__device__ __forceinline__ ull fma2(ull a, ull b, ull c) {
    ull d; asm("fma.rn.f32x2 %0, %1, %2, %3;" : "=l"(d) : "l"(a), "l"(b), "l"(c)); return d;
}
__device__ __forceinline__ ull add2(ull a, ull b) {
    ull d; asm("add.rn.f32x2 %0, %1, %2;" : "=l"(d) : "l"(a), "l"(b)); return d;
}
__device__ __forceinline__ float tanh_t(float x) {
    float t; asm("tanh.approx.f32 %0, %1;" : "=f"(t) : "f"(x)); return t;
}

// ---------------------------------------------------------------------------
// Kernel A: embedding gather + x @ W_ih^T + b -> paired-gate/paired-batch layout.
// ---------------------------------------------------------------------------
__global__ void gates_kernel(const int* __restrict__ data,
                             const int* __restrict__ lengths,
                             const float* __restrict__ emb,
                             const float* __restrict__ w_ih_f,
                             const float* __restrict__ b_f,
                             const float* __restrict__ w_ih_b,
                             const float* __restrict__ b_b) {
    __shared__ int tok[2][TCH];
    __shared__ float xs[2][TCH][16];

    const int b   = blockIdx.y;
    const int t0  = blockIdx.x * TCH;
    const int tid = threadIdx.x;
    const int L   = lengths[b];

    if (tid < 2 * TCH) {
        int d  = tid / TCH, tl = tid % TCH;
        int tg = t0 + tl;
        int src = (d == 0) ? tg : min(max(L - 1 - tg, 0), TT - 1);
        tok[d][tl] = data[b * TT + src];
    }
    __syncthreads();
    for (int i = tid; i < 2 * TCH * EE; i += blockDim.x) {
        int e  = i % EE;
        int tl = (i / EE) % TCH;
        int d  = i / (EE * TCH);
        xs[d][tl][e] = emb[(size_t)tok[d][tl] * EE + e];
    }
    __syncthreads();

    if (tid < 2 * GG) {
        const int d    = tid / GG;
        const int g    = tid % GG;
        const int gate = g / HH;        // 0..3 = i,f,g,o
        const int j    = g % HH;
        const int grp  = gate >> 1;
        const int s    = gate & 1;
        const float* w = d ? w_ih_b : w_ih_f;
        const float bias = (d ? b_b : b_f)[g];
        float wr[EE];
#pragma unroll
        for (int k = 0; k < EE; k++) wr[k] = w[g * EE + k];
        float* out = (float*)g_xg;
        const size_t comp = (size_t)(b & 1) * 2 + s;
#pragma unroll 4
        for (int tl = 0; tl < TCH; tl++) {
            float a = bias;
#pragma unroll
            for (int k = 0; k < EE; k++) a = fmaf(xs[d][tl][k], wr[k], a);
            size_t idx4 = (((size_t)(t0 + tl) * 2 + d) * 32 + (b >> 1)) * 32 + grp * 16 + j;
            out[idx4 * 4 + comp] = a;
        }
    }
}

// ---------------------------------------------------------------------------
// Kernel B: LSTM recurrence. One warp per (dir, batch-PAIR) -> 64 warps.
// Two independent chains per warp interleave to fill issue slots during
// each other's latency stalls. Recurrent weights shared (same dir).
// Lanes 0-15: gates {i,f}; lanes 16-31: gates {g,o}; butterfly xor-16 exchange.
// ---------------------------------------------------------------------------
__global__ void __launch_bounds__(32, 1)
lstm_rec_kernel(const float* __restrict__ h0,
                const float* __restrict__ c0,
                const float* __restrict__ w_hh_f,
                const float* __restrict__ w_hh_b,
                const int* __restrict__ lengths) {
    const int bp   = blockIdx.x & 31;
    const int dir  = blockIdx.x >> 5;
    const int b0i  = 2 * bp, b1i = 2 * bp + 1;
    const int lane = threadIdx.x;
    const int grp  = lane >> 4;
    const int jj   = lane & 15;
    const int jp   = (jj < HH) ? jj : 0;

    const float* whh = dir ? w_hh_b : w_hh_f;
    float* hsbase = dir ? g_hsbr : g_hsf;
    float* hso0 = hsbase + ((size_t)b0i * 16 + jj) * TT;
    float* hso1 = hsbase + ((size_t)b1i * 16 + jj) * TT;
    const int L0 = lengths[b0i], L1 = lengths[b1i];
    const int Lmax = max(L0, L1);

    // k-pair packed recurrent weights (shared by both chains).
    const int rowA = (grp ? 2 * HH : 0) + jp;
    const int rowB = (grp ? 3 * HH : HH) + jp;
    ull wA[8], wB[8];
#pragma unroll
    for (int p = 0; p < 8; p++) {
        float a0 = whh[rowA * HH + 2 * p];
        float a1 = (2 * p + 1 < HH) ? whh[rowA * HH + 2 * p + 1] : 0.0f;
        float b0v = whh[rowB * HH + 2 * p];
        float b1v = (2 * p + 1 < HH) ? whh[rowB * HH + 2 * p + 1] : 0.0f;
        if (jj == 15) { a0 = a1 = b0v = b1v = 0.0f; }
        wA[p] = pack2(a0, a1);
        wB[p] = pack2(b0v, b1v);
    }
    const float sclA = grp ? 1.0f : 0.5f;
    const float mulA = grp ? 1.0f : 0.5f;
    const float addA = grp ? 0.0f : 0.5f;

    float hj0 = h0[((size_t)dir * BB + b0i) * HH + jp];
    float cc0 = c0[((size_t)dir * BB + b0i) * HH + jp];
    float hj1 = h0[((size_t)dir * BB + b1i) * HH + jp];
    float cc1 = c0[((size_t)dir * BB + b1i) * HH + jp];
    if (jj == 15) { hj0 = 0.0f; hj1 = 0.0f; }

    ull hp0[8], hp1[8];
    {
        float s0 = (jj == 15) ? 0.0f : hj0;
        float s1 = (jj == 15) ? 0.0f : hj1;
#pragma unroll
        for (int p = 0; p < 8; p++) {
            hp0[p] = pack2(__shfl_sync(0xffffffffu, s0, 2 * p),
                           __shfl_sync(0xffffffffu, s0, 2 * p + 1));
            hp1[p] = pack2(__shfl_sync(0xffffffffu, s1, 2 * p),
                           __shfl_sync(0xffffffffu, s1, 2 * p + 1));
        }
    }

    // One float4 per step feeds both chains.
    const float4* xgp = g_xg + (size_t)dir * 1024 + (size_t)bp * 32 + lane;
    const size_t stride = 2048;  // float4s per timestep

    float4 pf[UU];
#pragma unroll
    for (int u = 0; u < UU; u++) pf[u] = xgp[(size_t)u * stride];

    float ha0 = 0, ha1 = 0, ha2 = 0;   // store batch, chain 0
    float hc0 = 0, hc1 = 0, hc2 = 0;   // store batch, chain 1

    for (int t = 0; t < Lmax; t += UU) {
#pragma unroll
        for (int u = 0; u < UU; u++) {
            float4 pv = pf[u];
            pf[u] = xgp[(size_t)(t + u + UU) * stride];

            // ---- chain 0 dot ----
            ull A0 = pack2(pv.x, 0.0f), A1 = 0;
            ull B0 = pack2(pv.y, 0.0f), B1 = 0;
            // ---- chain 1 dot ----
            ull C0 = pack2(pv.z, 0.0f), C1 = 0;
            ull D0 = pack2(pv.w, 0.0f), D1 = 0;
#pragma unroll
            for (int p = 0; p < 4; p++) {
                A0 = fma2(hp0[p], wA[p], A0);
                B0 = fma2(hp0[p], wB[p], B0);
                C0 = fma2(hp1[p], wA[p], C0);
                D0 = fma2(hp1[p], wB[p], D0);
            }
#pragma unroll
            for (int p = 4; p < 8; p++) {
                A1 = fma2(hp0[p], wA[p], A1);
                B1 = fma2(hp0[p], wB[p], B1);
                C1 = fma2(hp1[p], wA[p], C1);
                D1 = fma2(hp1[p], wB[p], D1);
            }
            float al, ah, bl, bh, cl, ch, dl, dh;
            unpack2(al, ah, add2(A0, A1)); unpack2(bl, bh, add2(B0, B1));
            unpack2(cl, ch, add2(C0, C1)); unpack2(dl, dh, add2(D0, D1));
            float aA0 = al + ah, aB0 = bl + bh;
            float aA1 = cl + ch, aB1 = dl + dh;

            float rA0 = fmaf(mulA, tanh_t(aA0 * sclA), addA);
            float rB0 = fmaf(0.5f, tanh_t(aB0 * 0.5f), 0.5f);
            float rA1 = fmaf(mulA, tanh_t(aA1 * sclA), addA);
            float rB1 = fmaf(0.5f, tanh_t(aB1 * 0.5f), 0.5f);

            float xA0 = __shfl_xor_sync(0xffffffffu, rA0, 16);
            float xB0 = __shfl_xor_sync(0xffffffffu, rB0, 16);
            float xA1 = __shfl_xor_sync(0xffffffffu, rA1, 16);
            float xB1 = __shfl_xor_sync(0xffffffffu, rB1, 16);

            cc0 = fmaf(rB0, cc0, rA0 * xA0);
            hj0 = xB0 * tanh_t(cc0);
            cc1 = fmaf(rB1, cc1, rA1 * xA1);
            hj1 = xB1 * tanh_t(cc1);

            float s0 = (jj == 15) ? 0.0f : hj0;
            float s1 = (jj == 15) ? 0.0f : hj1;
#pragma unroll
            for (int p = 0; p < 8; p++) {
                hp0[p] = pack2(__shfl_sync(0xffffffffu, s0, 2 * p),
                               __shfl_sync(0xffffffffu, s0, 2 * p + 1));
                hp1[p] = pack2(__shfl_sync(0xffffffffu, s1, 2 * p),
                               __shfl_sync(0xffffffffu, s1, 2 * p + 1));
            }

            // Batched stores every 4 steps (over-stores past L are never read;
            // max index ceil8(Lmax)-1 <= TT-1).
            int ph = u & 3;
            if (ph == 0)      { ha0 = hj0; hc0 = hj1; }
            else if (ph == 1) { ha1 = hj0; hc1 = hj1; }
            else if (ph == 2) { ha2 = hj0; hc2 = hj1; }
            else {
                int tb = t + u - 3;
                if (lane < HH) {
                    if (tb < L0) *(float4*)(hso0 + tb) = make_float4(ha0, ha1, ha2, hj0);
                    if (tb < L1) *(float4*)(hso1 + tb) = make_float4(hc0, hc1, hc2, hj1);
                }
            }
        }
    }
}

// ---------------------------------------------------------------------------
// Kernel C: out[b,t,:] = valid ? [hf|hb] @ lin_w^T + lin_b : lin_b
// ---------------------------------------------------------------------------
__global__ void out_kernel(const float* __restrict__ lin_w,
                           const float* __restrict__ lin_b,
                           const int* __restrict__ lengths,
                           float* __restrict__ out) {
    __shared__ __align__(16) float sw[45 * 32];
    __shared__ float sb[45];
    const int tid = threadIdx.x;
    for (int i = tid; i < 45 * 32; i += blockDim.x) {
        int o = i >> 5, k = i & 31;
        sw[i] = (k < 30) ? lin_w[o * 30 + k] : 0.0f;
    }
    if (tid < 45) sb[tid] = lin_b[tid];
    __syncthreads();

    const int idx = blockIdx.x * blockDim.x + tid;
    if (idx >= BB * TT) return;
    const int b = idx >> 12;
    const int t = idx & (TT - 1);
    const int L = lengths[b];

    float hx[32];
#pragma unroll
    for (int k = 0; k < 32; k++) hx[k] = 0.0f;
    if (t < L) {
        const int rev = L - 1 - t;
#pragma unroll
        for (int k = 0; k < HH; k++) {
            hx[k]      = g_hsf[((size_t)b * 16 + k) * TT + t];
            hx[15 + k] = g_hsbr[((size_t)b * 16 + k) * TT + rev];
        }
    }

    float* op = out + (size_t)idx * 45;
#pragma unroll
    for (int o = 0; o < 45; o++) {
        float a = sb[o];
#pragma unroll
        for (int q = 0; q < 8; q++) {
            float4 w4 = *reinterpret_cast<const float4*>(&sw[o * 32 + q * 4]);
            a = fmaf(hx[q * 4 + 0], w4.x, a);
            a = fmaf(hx[q * 4 + 1], w4.y, a);
            a = fmaf(hx[q * 4 + 2], w4.z, a);
            a = fmaf(hx[q * 4 + 3], w4.w, a);
        }
        op[o] = a;
    }
}

// ---------------------------------------------------------------------------
extern "C" void kernel_launch(void* const* d_in, const int* in_sizes, int n_in,
                              void* d_out, int out_size) {
    int off = (n_in >= 14) ? 1 : 0;
    const int*   data    = (const int*)d_in[0];
    const int*   lengths = (const int*)d_in[1 + off];
    const float* emb     = (const float*)d_in[2 + off];
    const float* h0      = (const float*)d_in[3 + off];
    const float* c0      = (const float*)d_in[4 + off];
    const float* w_ih_f  = (const float*)d_in[5 + off];
    const float* w_hh_f  = (const float*)d_in[6 + off];
    const float* b_f     = (const float*)d_in[7 + off];
    const float* w_ih_b  = (const float*)d_in[8 + off];
    const float* w_hh_b  = (const float*)d_in[9 + off];
    const float* b_b     = (const float*)d_in[10 + off];
    const float* lin_w   = (const float*)d_in[11 + off];
    const float* lin_b   = (const float*)d_in[12 + off];
    float* out = (float*)d_out;

    gates_kernel<<<dim3(TT / TCH, BB), 128>>>(data, lengths, emb, w_ih_f, b_f, w_ih_b, b_b);
    lstm_rec_kernel<<<64, 32>>>(h0, c0, w_hh_f, w_hh_b, lengths);
    out_kernel<<<(BB * TT + 127) / 128, 128>>>(lin_w, lin_b, lengths, out);
}

// round 6
// speedup vs baseline: 1.3561x; 1.3561x over previous
#include <cuda_runtime.h>
#include <cstdint>

#define BB 64
#define TT 4096
#define HH 15
#define EE 15
#define GG 60   /* 4*H */
#define TCH 32
#define UU 8    /* prefetch depth (steps) in the recurrence */

// Gate preacts: one float4 per (t, dir, batch-pair, lane):
//   lane = grp*16 + j;  float4 = {gA(b0), gB(b0), gA(b1), gB(b1)}
//   grp0: gA=0.5*i_j, gB=0.5*f_j ; grp1: gA=g_j, gB=0.5*o_j  (0.5 pre-folded)
// j==15 slots never written -> stay zero. Padded 2*UU timesteps for prefetch.
__device__ float4 g_xg[(size_t)(TT + 2 * UU) * 2 * 32 * 32];
// Hidden states, [b][j][t] layout. Backward stored in step-time (rev at read).
__device__ float g_hsf[(size_t)BB * 16 * TT];
__device__ float g_hsbr[(size_t)BB * 16 * TT];

typedef unsigned long long ull;

__device__ __forceinline__ ull pack2(float lo, float hi) {
    ull r; asm("mov.b64 %0, {%1,%2};" : "=l"(r) : "f"(lo), "f"(hi)); return r;
}
__device__ __forceinline__ void unpack2(float& lo, float& hi, ull v) {
    asm("mov.b64 {%0,%1}, %2;" : "=f"(lo), "=f"(hi) : "l"(v));
}
__device__ __forceinline__ ull fma2(ull a, ull b, ull c) {
    ull d; asm("fma.rn.f32x2 %0, %1, %2, %3;" : "=l"(d) : "l"(a), "l"(b), "l"(c)); return d;
}
__device__ __forceinline__ ull add2(ull a, ull b) {
    ull d; asm("add.rn.f32x2 %0, %1, %2;" : "=l"(d) : "l"(a), "l"(b)); return d;
}
__device__ __forceinline__ float tanh_t(float x) {
    float t; asm("tanh.approx.f32 %0, %1;" : "=f"(t) : "f"(x)); return t;
}

// ---------------------------------------------------------------------------
// Kernel A: embedding gather + x @ W_ih^T + b -> paired layout, coalesced
// float4 stores. Block owns (batch-pair, TCH timesteps, both dirs).
// Thread (half, d, grp, j) computes gates (gA,gB) for both batches of the pair.
// ---------------------------------------------------------------------------
__global__ void gates_kernel(const int* __restrict__ data,
                             const int* __restrict__ lengths,
                             const float* __restrict__ emb,
                             const float* __restrict__ w_ih_f,
                             const float* __restrict__ b_f,
                             const float* __restrict__ w_ih_b,
                             const float* __restrict__ b_b) {
    __shared__ int tok[4][TCH];          // [d*2+bo][tl]
    __shared__ float xs[4][TCH][16];

    const int bp  = blockIdx.y;
    const int t0  = blockIdx.x * TCH;
    const int tid = threadIdx.x;

    {   // token gather: 128 threads = 4 seqs x 32 timesteps
        int s2 = tid >> 5, tl = tid & 31;
        int d = s2 >> 1, bo = s2 & 1, b = 2 * bp + bo;
        int L = lengths[b];
        int tg = t0 + tl;
        int src = (d == 0) ? tg : min(max(L - 1 - tg, 0), TT - 1);
        tok[s2][tl] = data[b * TT + src];
    }
    __syncthreads();
    for (int i = tid; i < 4 * TCH * EE; i += 128) {
        int e = i % EE; int r = i / EE; int tl = r & 31; int s2 = r >> 5;
        xs[s2][tl][e] = emb[(size_t)tok[s2][tl] * EE + e];
    }
    __syncthreads();

    const int th   = tid & 63;
    const int half = tid >> 6;           // which 16-timestep half
    const int d    = th >> 5;
    const int slot = th & 31;
    const int grp  = slot >> 4;
    const int j    = slot & 15;
    if (j == 15) return;                 // padding slot stays zero

    const int gateA = 2 * grp;           // i or g
    const int gateB = 2 * grp + 1;       // f or o
    const float* w  = d ? w_ih_b : w_ih_f;
    const float* bv = d ? b_b : b_f;
    const float sA  = grp ? 1.0f : 0.5f; // gate g unscaled, i scaled
    float wa[EE], wb[EE];
#pragma unroll
    for (int k = 0; k < EE; k++) {
        wa[k] = w[(gateA * HH + j) * EE + k] * sA;
        wb[k] = w[(gateB * HH + j) * EE + k] * 0.5f;
    }
    const float biasA = bv[gateA * HH + j] * sA;
    const float biasB = bv[gateB * HH + j] * 0.5f;

    const int tlo = half * 16;
#pragma unroll 2
    for (int tl = tlo; tl < tlo + 16; tl++) {
        float a0 = biasA, bb0 = biasB, a1 = biasA, bb1 = biasB;
#pragma unroll
        for (int k = 0; k < EE; k++) {
            float x0 = xs[2 * d][tl][k], x1 = xs[2 * d + 1][tl][k];
            a0  = fmaf(x0, wa[k], a0);
            bb0 = fmaf(x0, wb[k], bb0);
            a1  = fmaf(x1, wa[k], a1);
            bb1 = fmaf(x1, wb[k], bb1);
        }
        g_xg[(((size_t)(t0 + tl) * 2 + d) * 32 + bp) * 32 + slot] =
            make_float4(a0, bb0, a1, bb1);
    }
}

// ---------------------------------------------------------------------------
// Kernel B: LSTM recurrence. One warp per (dir, batch) -> 128 warps.
// h broadcast via smem: lanes 0-14 STS h, all lanes reload as 4x LDS.128
// (ulonglong2 pairs) -- replaces 16 SHFL + 16 pack MOV per step.
// Lanes 0-15: gates {i,f}; lanes 16-31: {g,o}; butterfly xor-16 exchange.
// ---------------------------------------------------------------------------
__global__ void __launch_bounds__(32, 1)
lstm_rec_kernel(const float* __restrict__ h0,
                const float* __restrict__ c0,
                const float* __restrict__ w_hh_f,
                const float* __restrict__ w_hh_b,
                const int* __restrict__ lengths) {
    __shared__ __align__(16) float hsm[16];

    const int b    = blockIdx.x & (BB - 1);
    const int dir  = blockIdx.x >> 6;
    const int lane = threadIdx.x;
    const int grp  = lane >> 4;
    const int jj   = lane & 15;
    const int jp   = (jj < HH) ? jj : 0;

    const float* whh = dir ? w_hh_b : w_hh_f;
    float* hso = (dir ? g_hsbr : g_hsf) + ((size_t)b * 16 + jj) * TT;
    const int L = lengths[b];

    // k-pair packed recurrent weights, activation scale folded in.
    const int rowA = (grp ? 2 * HH : 0) + jp;
    const int rowB = (grp ? 3 * HH : HH) + jp;
    const float swA = grp ? 1.0f : 0.5f;
    ull wA[8], wB[8];
#pragma unroll
    for (int p = 0; p < 8; p++) {
        float a0 = whh[rowA * HH + 2 * p] * swA;
        float a1 = (2 * p + 1 < HH) ? whh[rowA * HH + 2 * p + 1] * swA : 0.0f;
        float b0 = whh[rowB * HH + 2 * p] * 0.5f;
        float b1 = (2 * p + 1 < HH) ? whh[rowB * HH + 2 * p + 1] * 0.5f : 0.0f;
        if (jj == 15) { a0 = a1 = b0 = b1 = 0.0f; }
        wA[p] = pack2(a0, a1);
        wB[p] = pack2(b0, b1);
    }
    const float mulA = grp ? 1.0f : 0.5f;
    const float addA = grp ? 0.0f : 0.5f;

    float hj = h0[((size_t)dir * BB + b) * HH + jp];
    float c  = c0[((size_t)dir * BB + b) * HH + jp];
    if (grp == 0) hsm[jj] = (jj < HH) ? hj : 0.0f;   // slot 15 pinned to 0
    __syncwarp();

    // Gate stream: float2 {gA,gB} slice of the pair-layout float4 array.
    const float2* xgp = (const float2*)g_xg
        + (((size_t)dir * 32 + (b >> 1)) * 32 + lane) * 2 + (b & 1);
    const size_t stride2 = (size_t)2 * 32 * 32 * 2;   // float2s per timestep

    float2 pf[UU];
#pragma unroll
    for (int u = 0; u < UU; u++) pf[u] = xgp[(size_t)u * stride2];

    float ha0 = 0, ha1 = 0, ha2 = 0;

    for (int t = 0; t < L; t += UU) {
#pragma unroll
        for (int u = 0; u < UU; u++) {
            float2 pv = pf[u];
            pf[u] = xgp[(size_t)(t + u + UU) * stride2];  // padding-safe refill

            // h pairs: 4x LDS.128 broadcast (conflict-free, N=1)
            ulonglong2 q0 = ((const ulonglong2*)hsm)[0];
            ulonglong2 q1 = ((const ulonglong2*)hsm)[1];
            ulonglong2 q2 = ((const ulonglong2*)hsm)[2];
            ulonglong2 q3 = ((const ulonglong2*)hsm)[3];

            ull A0 = pack2(pv.x, 0.0f), A1 = 0;
            ull B0 = pack2(pv.y, 0.0f), B1 = 0;
            A0 = fma2(q0.x, wA[0], A0);  B0 = fma2(q0.x, wB[0], B0);
            A0 = fma2(q0.y, wA[1], A0);  B0 = fma2(q0.y, wB[1], B0);
            A0 = fma2(q1.x, wA[2], A0);  B0 = fma2(q1.x, wB[2], B0);
            A0 = fma2(q1.y, wA[3], A0);  B0 = fma2(q1.y, wB[3], B0);
            A1 = fma2(q2.x, wA[4], A1);  B1 = fma2(q2.x, wB[4], B1);
            A1 = fma2(q2.y, wA[5], A1);  B1 = fma2(q2.y, wB[5], B1);
            A1 = fma2(q3.x, wA[6], A1);  B1 = fma2(q3.x, wB[6], B1);
            A1 = fma2(q3.y, wA[7], A1);  B1 = fma2(q3.y, wB[7], B1);

            float al, ah, bl, bh;
            unpack2(al, ah, add2(A0, A1));
            unpack2(bl, bh, add2(B0, B1));
            float aA = al + ah, aB = bl + bh;

            // grp0: rA=sigmoid(i), rB=sigmoid(f); grp1: rA=tanh(g), rB=sigmoid(o)
            float rA = fmaf(mulA, tanh_t(aA), addA);
            float rB = fmaf(0.5f, tanh_t(aB), 0.5f);

            float xA = __shfl_xor_sync(0xffffffffu, rA, 16);
            float xB = __shfl_xor_sync(0xffffffffu, rB, 16);
            // grp0 view: rA=i, rB=f, xA=tanh(g), xB=sig(o)
            c  = fmaf(rB, c, rA * xA);
            hj = xB * tanh_t(c);

            if (lane < HH) hsm[lane] = hj;   // true h only (grp0 lanes 0-14)
            __syncwarp();

            // Batched STG.128 every 4 steps (over-stores past L never read;
            // max touched index = ceil8(L)-1 <= TT-1).
            int ph = u & 3;
            if (ph == 0)      ha0 = hj;
            else if (ph == 1) ha1 = hj;
            else if (ph == 2) ha2 = hj;
            else if (lane < HH)
                *(float4*)(hso + (t + u - 3)) = make_float4(ha0, ha1, ha2, hj);
        }
    }
}

// ---------------------------------------------------------------------------
// Kernel C: out[b,t,:] = valid ? [hf|hb] @ lin_w^T + lin_b : lin_b
// ---------------------------------------------------------------------------
__global__ void out_kernel(const float* __restrict__ lin_w,
                           const float* __restrict__ lin_b,
                           const int* __restrict__ lengths,
                           float* __restrict__ out) {
    __shared__ __align__(16) float sw[45 * 32];
    __shared__ float sb[45];
    const int tid = threadIdx.x;
    for (int i = tid; i < 45 * 32; i += blockDim.x) {
        int o = i >> 5, k = i & 31;
        sw[i] = (k < 30) ? lin_w[o * 30 + k] : 0.0f;
    }
    if (tid < 45) sb[tid] = lin_b[tid];
    __syncthreads();

    const int idx = blockIdx.x * blockDim.x + tid;
    if (idx >= BB * TT) return;
    const int b = idx >> 12;
    const int t = idx & (TT - 1);
    const int L = lengths[b];

    float hx[32];
#pragma unroll
    for (int k = 0; k < 32; k++) hx[k] = 0.0f;
    if (t < L) {
        const int rev = L - 1 - t;
#pragma unroll
        for (int k = 0; k < HH; k++) {
            hx[k]      = g_hsf[((size_t)b * 16 + k) * TT + t];
            hx[15 + k] = g_hsbr[((size_t)b * 16 + k) * TT + rev];
        }
    }

    float* op = out + (size_t)idx * 45;
#pragma unroll
    for (int o = 0; o < 45; o++) {
        float a = sb[o];
#pragma unroll
        for (int q = 0; q < 8; q++) {
            float4 w4 = *reinterpret_cast<const float4*>(&sw[o * 32 + q * 4]);
            a = fmaf(hx[q * 4 + 0], w4.x, a);
            a = fmaf(hx[q * 4 + 1], w4.y, a);
            a = fmaf(hx[q * 4 + 2], w4.z, a);
            a = fmaf(hx[q * 4 + 3], w4.w, a);
        }
        op[o] = a;
    }
}

// ---------------------------------------------------------------------------
extern "C" void kernel_launch(void* const* d_in, const int* in_sizes, int n_in,
                              void* d_out, int out_size) {
    int off = (n_in >= 14) ? 1 : 0;
    const int*   data    = (const int*)d_in[0];
    const int*   lengths = (const int*)d_in[1 + off];
    const float* emb     = (const float*)d_in[2 + off];
    const float* h0      = (const float*)d_in[3 + off];
    const float* c0      = (const float*)d_in[4 + off];
    const float* w_ih_f  = (const float*)d_in[5 + off];
    const float* w_hh_f  = (const float*)d_in[6 + off];
    const float* b_f     = (const float*)d_in[7 + off];
    const float* w_ih_b  = (const float*)d_in[8 + off];
    const float* w_hh_b  = (const float*)d_in[9 + off];
    const float* b_b     = (const float*)d_in[10 + off];
    const float* lin_w   = (const float*)d_in[11 + off];
    const float* lin_b   = (const float*)d_in[12 + off];
    float* out = (float*)d_out;

    gates_kernel<<<dim3(TT / TCH, 32), 128>>>(data, lengths, emb, w_ih_f, b_f, w_ih_b, b_b);
    lstm_rec_kernel<<<2 * BB, 32>>>(h0, c0, w_hh_f, w_hh_b, lengths);
    out_kernel<<<(BB * TT + 127) / 128, 128>>>(lin_w, lin_b, lengths, out);
}

// round 7
// speedup vs baseline: 1.4178x; 1.0455x over previous
#include <cuda_runtime.h>
#include <cstdint>

#define BB 64
#define TT 4096
#define HH 15
#define EE 15
#define TCH 32
#define UU 8    /* prefetch depth (steps) in the recurrence */

// Gate preacts: one float4 {0.5i, 0.5f, g, 0.5o} per (t, dir, batch-pair, lane),
// lane = bo*16 + j. j==15 slots never written -> stay zero.
// Padded 2*UU timesteps for deep prefetch over-reads.
__device__ float4 g_xg[(size_t)(TT + 2 * UU) * 2 * 32 * 32];
// Hidden states, [b][j][t] layout. Backward stored in step-time (rev at read).
__device__ float g_hsf[(size_t)BB * 16 * TT];
__device__ float g_hsbr[(size_t)BB * 16 * TT];

typedef unsigned long long ull;

__device__ __forceinline__ ull pack2(float lo, float hi) {
    ull r; asm("mov.b64 %0, {%1,%2};" : "=l"(r) : "f"(lo), "f"(hi)); return r;
}
__device__ __forceinline__ void unpack2(float& lo, float& hi, ull v) {
    asm("mov.b64 {%0,%1}, %2;" : "=f"(lo), "=f"(hi) : "l"(v));
}
__device__ __forceinline__ ull fma2(ull a, ull b, ull c) {
    ull d; asm("fma.rn.f32x2 %0, %1, %2, %3;" : "=l"(d) : "l"(a), "l"(b), "l"(c)); return d;
}
__device__ __forceinline__ ull add2(ull a, ull b) {
    ull d; asm("add.rn.f32x2 %0, %1, %2;" : "=l"(d) : "l"(a), "l"(b)); return d;
}
__device__ __forceinline__ float tanh_t(float x) {
    float t; asm("tanh.approx.f32 %0, %1;" : "=f"(t) : "f"(x)); return t;
}
__device__ __forceinline__ float red2(ull v) {
    float lo, hi; unpack2(lo, hi, v); return lo + hi;
}

// ---------------------------------------------------------------------------
// Kernel A: embedding gather + x @ W_ih^T + b -> {0.5i,0.5f,g,0.5o} float4
// per (t, dir, bp, bo*16+j). Coalesced STG.128.
// ---------------------------------------------------------------------------
__global__ void gates_kernel(const int* __restrict__ data,
                             const int* __restrict__ lengths,
                             const float* __restrict__ emb,
                             const float* __restrict__ w_ih_f,
                             const float* __restrict__ b_f,
                             const float* __restrict__ w_ih_b,
                             const float* __restrict__ b_b) {
    __shared__ int tok[4][TCH];          // [d*2+bo][tl]
    __shared__ float xs[4][TCH][16];

    const int bp  = blockIdx.y;
    const int t0  = blockIdx.x * TCH;
    const int tid = threadIdx.x;

    {   // token gather: 128 threads = 4 seqs x 32 timesteps
        int s2 = tid >> 5, tl = tid & 31;
        int d = s2 >> 1, bo = s2 & 1, b = 2 * bp + bo;
        int L = lengths[b];
        int tg = t0 + tl;
        int src = (d == 0) ? tg : min(max(L - 1 - tg, 0), TT - 1);
        tok[s2][tl] = data[b * TT + src];
    }
    __syncthreads();
    for (int i = tid; i < 4 * TCH * EE; i += 128) {
        int e = i % EE; int r = i / EE; int tl = r & 31; int s2 = r >> 5;
        xs[s2][tl][e] = emb[(size_t)tok[s2][tl] * EE + e];
    }
    __syncthreads();

    const int half = tid >> 6;           // 16-timestep half
    const int th   = tid & 63;
    const int d    = th >> 5;
    const int bo   = (th >> 4) & 1;
    const int j    = th & 15;
    if (j == 15) return;                 // padding slot stays zero

    const float* w  = d ? w_ih_b : w_ih_f;
    const float* bv = d ? b_b : b_f;
    float wi[EE], wf[EE], wg[EE], wo[EE];
#pragma unroll
    for (int k = 0; k < EE; k++) {
        wi[k] = w[(0 * HH + j) * EE + k] * 0.5f;
        wf[k] = w[(1 * HH + j) * EE + k] * 0.5f;
        wg[k] = w[(2 * HH + j) * EE + k];
        wo[k] = w[(3 * HH + j) * EE + k] * 0.5f;
    }
    const float bi = bv[0 * HH + j] * 0.5f;
    const float bf = bv[1 * HH + j] * 0.5f;
    const float bg = bv[2 * HH + j];
    const float bo2 = bv[3 * HH + j] * 0.5f;

    const int s2 = d * 2 + bo;
    const int tlo = half * 16;
#pragma unroll 2
    for (int tl = tlo; tl < tlo + 16; tl++) {
        float ai = bi, af = bf, ag = bg, ao = bo2;
#pragma unroll
        for (int k = 0; k < EE; k++) {
            float x = xs[s2][tl][k];
            ai = fmaf(x, wi[k], ai);
            af = fmaf(x, wf[k], af);
            ag = fmaf(x, wg[k], ag);
            ao = fmaf(x, wo[k], ao);
        }
        g_xg[(((size_t)(t0 + tl) * 2 + d) * 32 + bp) * 32 + bo * 16 + j] =
            make_float4(ai, af, ag, ao);
    }
}

// ---------------------------------------------------------------------------
// Kernel B: LSTM recurrence, lane-split dual chains. 64 warps (dir x bp).
// Lanes 0-15: batch 2bp units; lanes 16-31: batch 2bp+1 units. Each lane
// computes all 4 gates of its unit (no cross-lane gate exchange); one 16-shfl
// broadcast per warp-step serves both chains (per-lane source = grp*16+k).
// ---------------------------------------------------------------------------
__global__ void __launch_bounds__(32, 1)
lstm_rec_kernel(const float* __restrict__ h0,
                const float* __restrict__ c0,
                const float* __restrict__ w_hh_f,
                const float* __restrict__ w_hh_b,
                const int* __restrict__ lengths) {
    const int bp   = blockIdx.x & 31;
    const int dir  = blockIdx.x >> 5;
    const int lane = threadIdx.x;
    const int grp  = lane >> 4;          // which chain of the pair
    const int jj   = lane & 15;          // unit (15 = pad)
    const int jp   = (jj < HH) ? jj : 0;
    const int b    = 2 * bp + grp;
    const int base = grp << 4;           // shfl source base for my chain

    const float* whh = dir ? w_hh_b : w_hh_f;
    float* hso = (dir ? g_hsbr : g_hsf) + ((size_t)b * 16 + jj) * TT;
    const int L0 = lengths[2 * bp], L1 = lengths[2 * bp + 1];
    const int Lm = max(L0, L1);
    const int Lc = grp ? L1 : L0;

    // k-pair packed recurrent weights for all 4 gates (activation 0.5 folded).
    ull wi[8], wf[8], wg[8], wo[8];
#pragma unroll
    for (int p = 0; p < 8; p++) {
        bool hv = (2 * p + 1 < HH);
        wi[p] = pack2(whh[(0 * HH + jp) * HH + 2 * p] * 0.5f,
                      hv ? whh[(0 * HH + jp) * HH + 2 * p + 1] * 0.5f : 0.0f);
        wf[p] = pack2(whh[(1 * HH + jp) * HH + 2 * p] * 0.5f,
                      hv ? whh[(1 * HH + jp) * HH + 2 * p + 1] * 0.5f : 0.0f);
        wg[p] = pack2(whh[(2 * HH + jp) * HH + 2 * p],
                      hv ? whh[(2 * HH + jp) * HH + 2 * p + 1] : 0.0f);
        wo[p] = pack2(whh[(3 * HH + jp) * HH + 2 * p] * 0.5f,
                      hv ? whh[(3 * HH + jp) * HH + 2 * p + 1] * 0.5f : 0.0f);
    }

    float hj = h0[((size_t)dir * BB + b) * HH + jp];
    float c  = c0[((size_t)dir * BB + b) * HH + jp];
    if (jj == 15) { hj = 0.0f; c = 0.0f; }   // pad lane: exactly 0 forever

    ull hp[8];
#pragma unroll
    for (int p = 0; p < 8; p++)
        hp[p] = pack2(__shfl_sync(0xffffffffu, hj, base + 2 * p),
                      __shfl_sync(0xffffffffu, hj, base + 2 * p + 1));

    const float4* xgp = g_xg + (((size_t)dir) * 32 + bp) * 32 + lane;
    const size_t stride = 2048;   // float4s per timestep

    float4 pf[UU];
#pragma unroll
    for (int u = 0; u < UU; u++) pf[u] = xgp[(size_t)u * stride];

    float h0s = 0, h1s = 0, h2s = 0;

    for (int t = 0; t < Lm; t += UU) {
#pragma unroll
        for (int u = 0; u < UU; u++) {
            float4 pv = pf[u];
            pf[u] = xgp[(size_t)(t + u + UU) * stride];  // padding-safe refill

            ull Ai0 = pack2(pv.x, 0.0f), Ai1 = 0;
            ull Af0 = pack2(pv.y, 0.0f), Af1 = 0;
            ull Ag0 = pack2(pv.z, 0.0f), Ag1 = 0;
            ull Ao0 = pack2(pv.w, 0.0f), Ao1 = 0;
#pragma unroll
            for (int p = 0; p < 4; p++) {
                Ai0 = fma2(hp[p], wi[p], Ai0);
                Af0 = fma2(hp[p], wf[p], Af0);
                Ag0 = fma2(hp[p], wg[p], Ag0);
                Ao0 = fma2(hp[p], wo[p], Ao0);
            }
#pragma unroll
            for (int p = 4; p < 8; p++) {
                Ai1 = fma2(hp[p], wi[p], Ai1);
                Af1 = fma2(hp[p], wf[p], Af1);
                Ag1 = fma2(hp[p], wg[p], Ag1);
                Ao1 = fma2(hp[p], wo[p], Ao1);
            }
            float ai = red2(add2(Ai0, Ai1));
            float af = red2(add2(Af0, Af1));
            float ag = red2(add2(Ag0, Ag1));
            float ao = red2(add2(Ao0, Ao1));

            float si = fmaf(0.5f, tanh_t(ai), 0.5f);
            float sf = fmaf(0.5f, tanh_t(af), 0.5f);
            float so = fmaf(0.5f, tanh_t(ao), 0.5f);
            float tg = tanh_t(ag);
            c  = fmaf(sf, c, si * tg);
            hj = so * tanh_t(c);

#pragma unroll
            for (int p = 0; p < 8; p++)
                hp[p] = pack2(__shfl_sync(0xffffffffu, hj, base + 2 * p),
                              __shfl_sync(0xffffffffu, hj, base + 2 * p + 1));

            // Batched STG.128 every 4 steps (over-stores within row never read).
            int ph = u & 3;
            if (ph == 0)      h0s = hj;
            else if (ph == 1) h1s = hj;
            else if (ph == 2) h2s = hj;
            else {
                int tb = t + u - 3;
                if (jj < HH && tb < Lc)
                    *(float4*)(hso + tb) = make_float4(h0s, h1s, h2s, hj);
            }
        }
    }
}

// ---------------------------------------------------------------------------
// Kernel C: out[b,t,:] = valid ? [hf|hb] @ lin_w^T + lin_b : lin_b
// ---------------------------------------------------------------------------
__global__ void out_kernel(const float* __restrict__ lin_w,
                           const float* __restrict__ lin_b,
                           const int* __restrict__ lengths,
                           float* __restrict__ out) {
    __shared__ __align__(16) float sw[45 * 32];
    __shared__ float sb[45];
    const int tid = threadIdx.x;
    for (int i = tid; i < 45 * 32; i += blockDim.x) {
        int o = i >> 5, k = i & 31;
        sw[i] = (k < 30) ? lin_w[o * 30 + k] : 0.0f;
    }
    if (tid < 45) sb[tid] = lin_b[tid];
    __syncthreads();

    const int idx = blockIdx.x * blockDim.x + tid;
    if (idx >= BB * TT) return;
    const int b = idx >> 12;
    const int t = idx & (TT - 1);
    const int L = lengths[b];

    float hx[32];
#pragma unroll
    for (int k = 0; k < 32; k++) hx[k] = 0.0f;
    if (t < L) {
        const int rev = L - 1 - t;
#pragma unroll
        for (int k = 0; k < HH; k++) {
            hx[k]      = g_hsf[((size_t)b * 16 + k) * TT + t];
            hx[15 + k] = g_hsbr[((size_t)b * 16 + k) * TT + rev];
        }
    }

    float* op = out + (size_t)idx * 45;
#pragma unroll
    for (int o = 0; o < 45; o++) {
        float a = sb[o];
#pragma unroll
        for (int q = 0; q < 8; q++) {
            float4 w4 = *reinterpret_cast<const float4*>(&sw[o * 32 + q * 4]);
            a = fmaf(hx[q * 4 + 0], w4.x, a);
            a = fmaf(hx[q * 4 + 1], w4.y, a);
            a = fmaf(hx[q * 4 + 2], w4.z, a);
            a = fmaf(hx[q * 4 + 3], w4.w, a);
        }
        op[o] = a;
    }
}

// ---------------------------------------------------------------------------
extern "C" void kernel_launch(void* const* d_in, const int* in_sizes, int n_in,
                              void* d_out, int out_size) {
    int off = (n_in >= 14) ? 1 : 0;
    const int*   data    = (const int*)d_in[0];
    const int*   lengths = (const int*)d_in[1 + off];
    const float* emb     = (const float*)d_in[2 + off];
    const float* h0      = (const float*)d_in[3 + off];
    const float* c0      = (const float*)d_in[4 + off];
    const float* w_ih_f  = (const float*)d_in[5 + off];
    const float* w_hh_f  = (const float*)d_in[6 + off];
    const float* b_f     = (const float*)d_in[7 + off];
    const float* w_ih_b  = (const float*)d_in[8 + off];
    const float* w_hh_b  = (const float*)d_in[9 + off];
    const float* b_b     = (const float*)d_in[10 + off];
    const float* lin_w   = (const float*)d_in[11 + off];
    const float* lin_b   = (const float*)d_in[12 + off];
    float* out = (float*)d_out;

    gates_kernel<<<dim3(TT / TCH, 32), 128>>>(data, lengths, emb, w_ih_f, b_f, w_ih_b, b_b);
    lstm_rec_kernel<<<64, 32>>>(h0, c0, w_hh_f, w_hh_b, lengths);
    out_kernel<<<(BB * TT + 127) / 128, 128>>>(lin_w, lin_b, lengths, out);
}

// round 8
// speedup vs baseline: 1.4874x; 1.0491x over previous
#include <cuda_runtime.h>
#include <cstdint>

#define BB 64
#define TT 4096
#define HH 15
#define EE 15
#define TCH 32
#define UU 8    /* prefetch depth (steps) in the recurrence */

// Gate preacts: one float4 {0.5i, 0.5f, g, 0.5o} per (t, dir, batch-pair, lane),
// lane = bo*16 + j. j==15 slots never written -> stay zero.
// Padded 2*UU timesteps for deep prefetch over-reads.
__device__ float4 g_xg[(size_t)(TT + 2 * UU) * 2 * 32 * 32];
// Hidden states, [b][j][t] layout. Backward stored in step-time (rev at read).
__device__ float g_hsf[(size_t)BB * 16 * TT];
__device__ float g_hsbr[(size_t)BB * 16 * TT];

typedef unsigned long long ull;

__device__ __forceinline__ ull pack2(float lo, float hi) {
    ull r; asm("mov.b64 %0, {%1,%2};" : "=l"(r) : "f"(lo), "f"(hi)); return r;
}
__device__ __forceinline__ void unpack2(float& lo, float& hi, ull v) {
    asm("mov.b64 {%0,%1}, %2;" : "=f"(lo), "=f"(hi) : "l"(v));
}
__device__ __forceinline__ ull fma2(ull a, ull b, ull c) {
    ull d; asm("fma.rn.f32x2 %0, %1, %2, %3;" : "=l"(d) : "l"(a), "l"(b), "l"(c)); return d;
}
__device__ __forceinline__ ull add2(ull a, ull b) {
    ull d; asm("add.rn.f32x2 %0, %1, %2;" : "=l"(d) : "l"(a), "l"(b)); return d;
}
__device__ __forceinline__ float tanh_t(float x) {
    float t; asm("tanh.approx.f32 %0, %1;" : "=f"(t) : "f"(x)); return t;
}
__device__ __forceinline__ float red2(ull v) {
    float lo, hi; unpack2(lo, hi, v); return lo + hi;
}
// Ordered smem ops (volatile: program-order within the converged warp).
__device__ __forceinline__ void sts32(uint32_t addr, float v) {
    asm volatile("st.shared.f32 [%0], %1;" :: "r"(addr), "f"(v) : "memory");
}
__device__ __forceinline__ void lds_b64x2(uint32_t addr, ull& lo, ull& hi) {
    asm volatile("ld.shared.v2.b64 {%0,%1}, [%2];"
                 : "=l"(lo), "=l"(hi) : "r"(addr) : "memory");
}

// ---------------------------------------------------------------------------
// Kernel A: embedding gather + x @ W_ih^T + b -> {0.5i,0.5f,g,0.5o} float4
// per (t, dir, bp, bo*16+j). Coalesced STG.128.
// ---------------------------------------------------------------------------
__global__ void gates_kernel(const int* __restrict__ data,
                             const int* __restrict__ lengths,
                             const float* __restrict__ emb,
                             const float* __restrict__ w_ih_f,
                             const float* __restrict__ b_f,
                             const float* __restrict__ w_ih_b,
                             const float* __restrict__ b_b) {
    __shared__ int tok[4][TCH];          // [d*2+bo][tl]
    __shared__ float xs[4][TCH][16];

    const int bp  = blockIdx.y;
    const int t0  = blockIdx.x * TCH;
    const int tid = threadIdx.x;

    {   // token gather: 128 threads = 4 seqs x 32 timesteps
        int s2 = tid >> 5, tl = tid & 31;
        int d = s2 >> 1, bo = s2 & 1, b = 2 * bp + bo;
        int L = lengths[b];
        int tg = t0 + tl;
        int src = (d == 0) ? tg : min(max(L - 1 - tg, 0), TT - 1);
        tok[s2][tl] = data[b * TT + src];
    }
    __syncthreads();
    for (int i = tid; i < 4 * TCH * EE; i += 128) {
        int e = i % EE; int r = i / EE; int tl = r & 31; int s2 = r >> 5;
        xs[s2][tl][e] = emb[(size_t)tok[s2][tl] * EE + e];
    }
    __syncthreads();

    const int half = tid >> 6;           // 16-timestep half
    const int th   = tid & 63;
    const int d    = th >> 5;
    const int bo   = (th >> 4) & 1;
    const int j    = th & 15;
    if (j == 15) return;                 // padding slot stays zero

    const float* w  = d ? w_ih_b : w_ih_f;
    const float* bv = d ? b_b : b_f;
    float wi[EE], wf[EE], wg[EE], wo[EE];
#pragma unroll
    for (int k = 0; k < EE; k++) {
        wi[k] = w[(0 * HH + j) * EE + k] * 0.5f;
        wf[k] = w[(1 * HH + j) * EE + k] * 0.5f;
        wg[k] = w[(2 * HH + j) * EE + k];
        wo[k] = w[(3 * HH + j) * EE + k] * 0.5f;
    }
    const float bi = bv[0 * HH + j] * 0.5f;
    const float bf = bv[1 * HH + j] * 0.5f;
    const float bg = bv[2 * HH + j];
    const float bo2 = bv[3 * HH + j] * 0.5f;

    const int s2 = d * 2 + bo;
    const int tlo = half * 16;
#pragma unroll 2
    for (int tl = tlo; tl < tlo + 16; tl++) {
        float ai = bi, af = bf, ag = bg, ao = bo2;
#pragma unroll
        for (int k = 0; k < EE; k++) {
            float x = xs[s2][tl][k];
            ai = fmaf(x, wi[k], ai);
            af = fmaf(x, wf[k], af);
            ag = fmaf(x, wg[k], ag);
            ao = fmaf(x, wo[k], ao);
        }
        g_xg[(((size_t)(t0 + tl) * 2 + d) * 32 + bp) * 32 + bo * 16 + j] =
            make_float4(ai, af, ag, ao);
    }
}

// ---------------------------------------------------------------------------
// Kernel B: LSTM recurrence, lane-split dual chains + sync-free smem
// h-broadcast. 64 warps (dir x bp). Lanes 0-15: batch 2bp; lanes 16-31:
// batch 2bp+1. Each lane computes all 4 gates of its unit. Broadcast:
// 1 STS (all 32 lanes) + 4 LDS.v2.b64 per warp-step serves both chains;
// the warp body is branch-free so the warp stays converged and same-warp
// smem program order makes the round trip race-free without syncwarp.
// ---------------------------------------------------------------------------
__global__ void __launch_bounds__(32, 1)
lstm_rec_kernel(const float* __restrict__ h0,
                const float* __restrict__ c0,
                const float* __restrict__ w_hh_f,
                const float* __restrict__ w_hh_b,
                const int* __restrict__ lengths) {
    __shared__ __align__(16) float hsm[32];   // [grp*16 + j]

    const int bp   = blockIdx.x & 31;
    const int dir  = blockIdx.x >> 5;
    const int lane = threadIdx.x;
    const int grp  = lane >> 4;          // which chain of the pair
    const int jj   = lane & 15;          // unit (15 = pad)
    const int jp   = (jj < HH) ? jj : 0;
    const int b    = 2 * bp + grp;

    const float* whh = dir ? w_hh_b : w_hh_f;
    float* hso = (dir ? g_hsbr : g_hsf) + ((size_t)b * 16 + jj) * TT;
    const int L0 = lengths[2 * bp], L1 = lengths[2 * bp + 1];
    const int Lm = max(L0, L1);

    // k-pair packed recurrent weights for all 4 gates (activation 0.5 folded).
    ull wi[8], wf[8], wg[8], wo[8];
#pragma unroll
    for (int p = 0; p < 8; p++) {
        bool hv = (2 * p + 1 < HH);
        float z = (jj == 15) ? 0.0f : 1.0f;
        wi[p] = pack2(whh[(0 * HH + jp) * HH + 2 * p] * 0.5f * z,
                      hv ? whh[(0 * HH + jp) * HH + 2 * p + 1] * 0.5f * z : 0.0f);
        wf[p] = pack2(whh[(1 * HH + jp) * HH + 2 * p] * 0.5f * z,
                      hv ? whh[(1 * HH + jp) * HH + 2 * p + 1] * 0.5f * z : 0.0f);
        wg[p] = pack2(whh[(2 * HH + jp) * HH + 2 * p] * z,
                      hv ? whh[(2 * HH + jp) * HH + 2 * p + 1] * z : 0.0f);
        wo[p] = pack2(whh[(3 * HH + jp) * HH + 2 * p] * 0.5f * z,
                      hv ? whh[(3 * HH + jp) * HH + 2 * p + 1] * 0.5f * z : 0.0f);
    }

    float hj = h0[((size_t)dir * BB + b) * HH + jp];
    float c  = c0[((size_t)dir * BB + b) * HH + jp];
    if (jj == 15) { hj = 0.0f; c = 0.0f; }   // pad lane: stays ~0, weight 0

    const uint32_t sbase = (uint32_t)__cvta_generic_to_shared(hsm);
    const uint32_t s_st  = sbase + lane * 4;
    const uint32_t s_ld  = sbase + (grp << 6);

    sts32(s_st, hj);                     // initial broadcast fill

    const float4* xgp = g_xg + (((size_t)dir) * 32 + bp) * 32 + lane;
    const size_t stride = 2048;   // float4s per timestep

    float4 pf[UU];
#pragma unroll
    for (int u = 0; u < UU; u++) pf[u] = xgp[(size_t)u * stride];

    float h0s = 0, h1s = 0, h2s = 0;
    const bool wr_en = (jj < HH);

    for (int t = 0; t < Lm; t += UU) {
#pragma unroll
        for (int u = 0; u < UU; u++) {
            float4 pv = pf[u];
            pf[u] = xgp[(size_t)(t + u + UU) * stride];  // padding-safe refill

            // h pairs for MY chain: 4x LDS.128 (after prior STS, in order)
            ull q0, q1, q2, q3, q4, q5, q6, q7;
            lds_b64x2(s_ld,      q0, q1);
            lds_b64x2(s_ld + 16, q2, q3);
            lds_b64x2(s_ld + 32, q4, q5);
            lds_b64x2(s_ld + 48, q6, q7);

            ull Ai0 = pack2(pv.x, 0.0f), Ai1 = 0;
            ull Af0 = pack2(pv.y, 0.0f), Af1 = 0;
            ull Ag0 = pack2(pv.z, 0.0f), Ag1 = 0;
            ull Ao0 = pack2(pv.w, 0.0f), Ao1 = 0;
            Ai0 = fma2(q0, wi[0], Ai0);  Af0 = fma2(q0, wf[0], Af0);
            Ag0 = fma2(q0, wg[0], Ag0);  Ao0 = fma2(q0, wo[0], Ao0);
            Ai0 = fma2(q1, wi[1], Ai0);  Af0 = fma2(q1, wf[1], Af0);
            Ag0 = fma2(q1, wg[1], Ag0);  Ao0 = fma2(q1, wo[1], Ao0);
            Ai0 = fma2(q2, wi[2], Ai0);  Af0 = fma2(q2, wf[2], Af0);
            Ag0 = fma2(q2, wg[2], Ag0);  Ao0 = fma2(q2, wo[2], Ao0);
            Ai0 = fma2(q3, wi[3], Ai0);  Af0 = fma2(q3, wf[3], Af0);
            Ag0 = fma2(q3, wg[3], Ag0);  Ao0 = fma2(q3, wo[3], Ao0);
            Ai1 = fma2(q4, wi[4], Ai1);  Af1 = fma2(q4, wf[4], Af1);
            Ag1 = fma2(q4, wg[4], Ag1);  Ao1 = fma2(q4, wo[4], Ao1);
            Ai1 = fma2(q5, wi[5], Ai1);  Af1 = fma2(q5, wf[5], Af1);
            Ag1 = fma2(q5, wg[5], Ag1);  Ao1 = fma2(q5, wo[5], Ao1);
            Ai1 = fma2(q6, wi[6], Ai1);  Af1 = fma2(q6, wf[6], Af1);
            Ag1 = fma2(q6, wg[6], Ag1);  Ao1 = fma2(q6, wo[6], Ao1);
            Ai1 = fma2(q7, wi[7], Ai1);  Af1 = fma2(q7, wf[7], Af1);
            Ag1 = fma2(q7, wg[7], Ag1);  Ao1 = fma2(q7, wo[7], Ao1);

            float ai = red2(add2(Ai0, Ai1));
            float af = red2(add2(Af0, Af1));
            float ag = red2(add2(Ag0, Ag1));
            float ao = red2(add2(Ao0, Ao1));

            float si = fmaf(0.5f, tanh_t(ai), 0.5f);
            float sf = fmaf(0.5f, tanh_t(af), 0.5f);
            float so = fmaf(0.5f, tanh_t(ao), 0.5f);
            float tg = tanh_t(ag);
            c  = fmaf(sf, c, si * tg);
            hj = so * tanh_t(c);

            sts32(s_st, hj);             // publish for next step (in order)

            // Batched STG.128 every 4 steps; stores stay inside the TT row and
            // positions >= L are never read, so only jj<HH predicates the store.
            int ph = u & 3;
            if (ph == 0)      h0s = hj;
            else if (ph == 1) h1s = hj;
            else if (ph == 2) h2s = hj;
            else if (wr_en)
                *(float4*)(hso + (t + u - 3)) = make_float4(h0s, h1s, h2s, hj);
        }
    }
}

// ---------------------------------------------------------------------------
// Kernel C: out[b,t,:] = valid ? [hf|hb] @ lin_w^T + lin_b : lin_b
// ---------------------------------------------------------------------------
__global__ void out_kernel(const float* __restrict__ lin_w,
                           const float* __restrict__ lin_b,
                           const int* __restrict__ lengths,
                           float* __restrict__ out) {
    __shared__ __align__(16) float sw[45 * 32];
    __shared__ float sb[45];
    const int tid = threadIdx.x;
    for (int i = tid; i < 45 * 32; i += blockDim.x) {
        int o = i >> 5, k = i & 31;
        sw[i] = (k < 30) ? lin_w[o * 30 + k] : 0.0f;
    }
    if (tid < 45) sb[tid] = lin_b[tid];
    __syncthreads();

    const int idx = blockIdx.x * blockDim.x + tid;
    if (idx >= BB * TT) return;
    const int b = idx >> 12;
    const int t = idx & (TT - 1);
    const int L = lengths[b];

    float hx[32];
#pragma unroll
    for (int k = 0; k < 32; k++) hx[k] = 0.0f;
    if (t < L) {
        const int rev = L - 1 - t;
#pragma unroll
        for (int k = 0; k < HH; k++) {
            hx[k]      = g_hsf[((size_t)b * 16 + k) * TT + t];
            hx[15 + k] = g_hsbr[((size_t)b * 16 + k) * TT + rev];
        }
    }

    float* op = out + (size_t)idx * 45;
#pragma unroll
    for (int o = 0; o < 45; o++) {
        float a = sb[o];
#pragma unroll
        for (int q = 0; q < 8; q++) {
            float4 w4 = *reinterpret_cast<const float4*>(&sw[o * 32 + q * 4]);
            a = fmaf(hx[q * 4 + 0], w4.x, a);
            a = fmaf(hx[q * 4 + 1], w4.y, a);
            a = fmaf(hx[q * 4 + 2], w4.z, a);
            a = fmaf(hx[q * 4 + 3], w4.w, a);
        }
        op[o] = a;
    }
}

// ---------------------------------------------------------------------------
extern "C" void kernel_launch(void* const* d_in, const int* in_sizes, int n_in,
                              void* d_out, int out_size) {
    int off = (n_in >= 14) ? 1 : 0;
    const int*   data    = (const int*)d_in[0];
    const int*   lengths = (const int*)d_in[1 + off];
    const float* emb     = (const float*)d_in[2 + off];
    const float* h0      = (const float*)d_in[3 + off];
    const float* c0      = (const float*)d_in[4 + off];
    const float* w_ih_f  = (const float*)d_in[5 + off];
    const float* w_hh_f  = (const float*)d_in[6 + off];
    const float* b_f     = (const float*)d_in[7 + off];
    const float* w_ih_b  = (const float*)d_in[8 + off];
    const float* w_hh_b  = (const float*)d_in[9 + off];
    const float* b_b     = (const float*)d_in[10 + off];
    const float* lin_w   = (const float*)d_in[11 + off];
    const float* lin_b   = (const float*)d_in[12 + off];
    float* out = (float*)d_out;

    gates_kernel<<<dim3(TT / TCH, 32), 128>>>(data, lengths, emb, w_ih_f, b_f, w_ih_b, b_b);
    lstm_rec_kernel<<<64, 32>>>(h0, c0, w_hh_f, w_hh_b, lengths);
    out_kernel<<<(BB * TT + 127) / 128, 128>>>(lin_w, lin_b, lengths, out);
}